// round 3
// baseline (speedup 1.0000x reference)
#include <cuda_runtime.h>
#include <cuda_bf16.h>

// Problem constants
#define Bb 2
#define Ss 2048
#define Dd 256
#define Hh 8
#define NR (Bb*Ss)          // 4096 rows total

// Scratch (static __device__ globals: allocation-free per harness rules)
__device__ float g_Q[Bb*Ss*Dd];        // 4 MB
__device__ float g_K[Bb*Ss*Dd];        // 4 MB
__device__ float g_V[Bb*Ss*Dd];        // 4 MB
__device__ float g_q2[NR];
__device__ float g_k2[NR];
__device__ float g_d2[(size_t)Bb*Ss*Ss]; // 33.5 MB, causal part written

// ---------------------------------------------------------------------------
// Kernel 1: projections Q = p@Wq, K = p@Wk, V = e@Wv   (fp32 SGEMM 64x64x32)
// grid: (NR/64, Dd/64, 3)   block: 256
// ---------------------------------------------------------------------------
__global__ __launch_bounds__(256) void proj_kernel(
    const float* __restrict__ p, const float* __restrict__ e,
    const float* __restrict__ Wq, const float* __restrict__ Wk,
    const float* __restrict__ Wv)
{
    const int which = blockIdx.z;
    const float* src = (which == 2) ? e : p;
    const float* W   = (which == 0) ? Wq : (which == 1) ? Wk : Wv;
    float* dst       = (which == 0) ? g_Q : (which == 1) ? g_K : g_V;

    const int row0 = blockIdx.x * 64;
    const int col0 = blockIdx.y * 64;

    __shared__ float As[32][65];   // As[k][m]
    __shared__ float Bs[32][64];   // Bs[k][n]

    const int tid = threadIdx.x;
    const int tx = tid & 15;       // col group: cols tx + 16*j
    const int ty = tid >> 4;       // row group: rows ty*4 + i

    float acc[4][4] = {};

    for (int k0 = 0; k0 < Dd; k0 += 32) {
        for (int l = tid; l < 64*32; l += 256) {
            int k = l & 31, m = l >> 5;
            As[k][m] = src[(size_t)(row0 + m)*Dd + k0 + k];
        }
        for (int l = tid; l < 32*64; l += 256) {
            int n = l & 63, k = l >> 6;
            Bs[k][n] = W[(size_t)(k0 + k)*Dd + col0 + n];
        }
        __syncthreads();
        #pragma unroll
        for (int k = 0; k < 32; k++) {
            float a[4], b[4];
            #pragma unroll
            for (int i = 0; i < 4; i++) a[i] = As[k][ty*4 + i];
            #pragma unroll
            for (int j = 0; j < 4; j++) b[j] = Bs[k][tx + 16*j];
            #pragma unroll
            for (int i = 0; i < 4; i++)
                #pragma unroll
                for (int j = 0; j < 4; j++)
                    acc[i][j] += a[i] * b[j];
        }
        __syncthreads();
    }
    #pragma unroll
    for (int i = 0; i < 4; i++)
        #pragma unroll
        for (int j = 0; j < 4; j++)
            dst[(size_t)(row0 + ty*4 + i)*Dd + col0 + tx + 16*j] = acc[i][j];
}

// ---------------------------------------------------------------------------
// Kernel 2: row norms q2, k2. One warp per row.
// ---------------------------------------------------------------------------
__global__ __launch_bounds__(256) void norms_kernel()
{
    int warp = (blockIdx.x * blockDim.x + threadIdx.x) >> 5;
    int lane = threadIdx.x & 31;
    if (warp >= NR) return;
    const float* q = g_Q + (size_t)warp * Dd;
    const float* k = g_K + (size_t)warp * Dd;
    float sq = 0.f, sk = 0.f;
    for (int i = lane; i < Dd; i += 32) {
        float a = q[i]; sq += a * a;
        float b = k[i]; sk += b * b;
    }
    #pragma unroll
    for (int o = 16; o; o >>= 1) {
        sq += __shfl_xor_sync(0xFFFFFFFFu, sq, o);
        sk += __shfl_xor_sync(0xFFFFFFFFu, sk, o);
    }
    if (lane == 0) { g_q2[warp] = sq; g_k2[warp] = sk; }
}

// ---------------------------------------------------------------------------
// Kernel 3: d2[b,s,t] = max(q2[s]+k2[t]-2*Q_s.K_t, 0) for causal tiles only.
// grid: (Ss/64 (t), Ss/64 (s), Bb)
// ---------------------------------------------------------------------------
__global__ __launch_bounds__(256) void d2_kernel()
{
    const int b  = blockIdx.z;
    const int s0 = blockIdx.y * 64;
    const int t0 = blockIdx.x * 64;
    if (t0 > s0 + 63) return;   // fully above diagonal

    const float* Qb = g_Q + (size_t)b*Ss*Dd;
    const float* Kb = g_K + (size_t)b*Ss*Dd;

    __shared__ float As[32][65];  // Q:  As[k][m]
    __shared__ float Bs[32][65];  // K:  Bs[k][n]

    const int tid = threadIdx.x;
    const int tx = tid & 15;
    const int ty = tid >> 4;

    float acc[4][4] = {};
    for (int k0 = 0; k0 < Dd; k0 += 32) {
        for (int l = tid; l < 64*32; l += 256) {
            int k = l & 31, m = l >> 5;
            As[k][m] = Qb[(size_t)(s0 + m)*Dd + k0 + k];
        }
        for (int l = tid; l < 64*32; l += 256) {
            int k = l & 31, n = l >> 5;
            Bs[k][n] = Kb[(size_t)(t0 + n)*Dd + k0 + k];
        }
        __syncthreads();
        #pragma unroll
        for (int k = 0; k < 32; k++) {
            float a[4], bv[4];
            #pragma unroll
            for (int i = 0; i < 4; i++) a[i]  = As[k][ty*4 + i];
            #pragma unroll
            for (int j = 0; j < 4; j++) bv[j] = Bs[k][tx + 16*j];
            #pragma unroll
            for (int i = 0; i < 4; i++)
                #pragma unroll
                for (int j = 0; j < 4; j++)
                    acc[i][j] += a[i] * bv[j];
        }
        __syncthreads();
    }

    float* d2b = g_d2 + (size_t)b*Ss*Ss;
    #pragma unroll
    for (int i = 0; i < 4; i++) {
        int s = s0 + ty*4 + i;
        float q2v = g_q2[b*Ss + s];
        #pragma unroll
        for (int j = 0; j < 4; j++) {
            int t = t0 + tx + 16*j;
            float v = q2v + g_k2[b*Ss + t] - 2.0f * acc[i][j];
            d2b[(size_t)s*Ss + t] = fmaxf(v, 0.0f);
        }
    }
}

// ---------------------------------------------------------------------------
// Kernel 4: O[b,h,s,:] = sum_{t<=s} exp(alpha_h * d2[b,s,t]) * V[b,t,:]
// Head dedup: block for head h runs only if h is the FIRST head with its gamma
// value; the leader writes the result to every head with equal gamma.
// grid: (Ss/64 (s_tile, reversed for balance), Dd/64 (d chunk), Bb*Hh)
// ---------------------------------------------------------------------------
__global__ __launch_bounds__(256) void attn_kernel(
    const float* __restrict__ gamma, float* __restrict__ out)
{
    const int s_tile = gridDim.x - 1 - blockIdx.x;  // longest work first
    const int dchunk = blockIdx.y;
    const int bh = blockIdx.z;
    const int b = bh >> 3, h = bh & 7;

    const float gh = gamma[h];
    for (int h2 = 0; h2 < h; h2++)
        if (gamma[h2] == gh) return;                // not the leader for this gamma
    const float coef = -1.0f / (-2.0f * gh + 1e-6f);

    const int s0 = s_tile * 64;
    const int d0 = dchunk * 64;

    __shared__ float Ps[64][65];   // Ps[r][t]
    __shared__ float Vs[64][64];   // Vs[t][c]

    const int tid = threadIdx.x;
    const int tx = tid & 15;       // cols c = tx + 16*j
    const int ty = tid >> 4;       // rows r = ty*4 + i

    float acc[4][4] = {};

    const float* Vb  = g_V  + (size_t)b*Ss*Dd;
    const float* d2b = g_d2 + (size_t)b*Ss*Ss;

    for (int t0 = 0; t0 <= s0; t0 += 64) {
        const bool diag = (t0 == s0);
        // load + exp the d2 tile
        for (int l = tid; l < 64*64; l += 256) {
            int c = l & 63, r = l >> 6;
            float d2v = d2b[(size_t)(s0 + r)*Ss + t0 + c];
            float pv = __expf(coef * d2v);
            if (diag && (c > r)) pv = 0.0f;        // causal mask inside diagonal tile
            Ps[r][c] = pv;
        }
        // load V tile chunk
        for (int l = tid; l < 64*64; l += 256) {
            int c = l & 63, r = l >> 6;
            Vs[r][c] = Vb[(size_t)(t0 + r)*Dd + d0 + c];
        }
        __syncthreads();
        #pragma unroll 4
        for (int t = 0; t < 64; t++) {
            float pv[4], vv[4];
            #pragma unroll
            for (int i = 0; i < 4; i++) pv[i] = Ps[ty*4 + i][t];
            #pragma unroll
            for (int j = 0; j < 4; j++) vv[j] = Vs[t][tx + 16*j];
            #pragma unroll
            for (int i = 0; i < 4; i++)
                #pragma unroll
                for (int j = 0; j < 4; j++)
                    acc[i][j] += pv[i] * vv[j];
        }
        __syncthreads();
    }

    // write to every head sharing this gamma
    for (int h2 = h; h2 < Hh; h2++) {
        if (gamma[h2] != gh) continue;
        float* o = out + ((size_t)(b*Hh + h2)*Ss)*Dd;
        #pragma unroll
        for (int i = 0; i < 4; i++)
            #pragma unroll
            for (int j = 0; j < 4; j++)
                o[(size_t)(s0 + ty*4 + i)*Dd + d0 + tx + 16*j] = acc[i][j];
    }
}

// ---------------------------------------------------------------------------
extern "C" void kernel_launch(void* const* d_in, const int* in_sizes, int n_in,
                              void* d_out, int out_size)
{
    // metadata order: x, e, p, W_q, W_k, W_v, gamma   (x unused: use_ppe path)
    const float* e     = (const float*)d_in[1];
    const float* p     = (const float*)d_in[2];
    const float* Wq    = (const float*)d_in[3];
    const float* Wk    = (const float*)d_in[4];
    const float* Wv    = (const float*)d_in[5];
    const float* gamma = (const float*)d_in[6];
    float* out = (float*)d_out;

    dim3 gproj(NR/64, Dd/64, 3);
    proj_kernel<<<gproj, 256>>>(p, e, Wq, Wk, Wv);

    norms_kernel<<<(NR*32)/256, 256>>>();

    dim3 gd2(Ss/64, Ss/64, Bb);
    d2_kernel<<<gd2, 256>>>();

    dim3 gattn(Ss/64, Dd/64, Bb*Hh);
    attn_kernel<<<gattn, 256>>>(gamma, out);
}

// round 4
// speedup vs baseline: 1.8963x; 1.8963x over previous
#include <cuda_runtime.h>
#include <cuda_bf16.h>

// Problem constants
#define Bb 2
#define Ss 2048
#define Dd 256
#define Hh 8
#define NR (Bb*Ss)          // 4096 rows total

// Scratch (static __device__ globals: allocation-free per harness rules)
__device__ float g_Q[Bb*Ss*Dd];        // 4 MB
__device__ float g_K[Bb*Ss*Dd];        // 4 MB
__device__ float g_V[Bb*Ss*Dd];        // 4 MB
__device__ float g_q2[NR];
__device__ float g_k2[NR];
__device__ float g_d2[(size_t)Bb*Ss*Ss]; // 33.5 MB, causal part written

// ---------------------------------------------------------------------------
// Kernel 1: projections Q = p@Wq, K = p@Wk, V = e@Wv (fp32 SGEMM 64x64x32,
// float4 microtile). grid: (NR/64, Dd/64, 3)  block: 256
// ---------------------------------------------------------------------------
__global__ __launch_bounds__(256) void proj_kernel(
    const float* __restrict__ p, const float* __restrict__ e,
    const float* __restrict__ Wq, const float* __restrict__ Wk,
    const float* __restrict__ Wv)
{
    const int which = blockIdx.z;
    const float* src = (which == 2) ? e : p;
    const float* W   = (which == 0) ? Wq : (which == 1) ? Wk : Wv;
    float* dst       = (which == 0) ? g_Q : (which == 1) ? g_K : g_V;

    const int row0 = blockIdx.x * 64;
    const int col0 = blockIdx.y * 64;

    __shared__ float As[32][68];   // As[k][m], padded for float4 + bank spread
    __shared__ float Bs[32][68];   // Bs[k][n]

    const int tid = threadIdx.x;
    const int tx = tid & 15;       // cols: tx*4 + j  (contiguous float4)
    const int ty = tid >> 4;       // rows: ty*4 + i  (contiguous float4)

    float acc[4][4] = {};

    for (int k0 = 0; k0 < Dd; k0 += 32) {
        for (int l = tid; l < 64*32; l += 256) {
            int k = l & 31, m = l >> 5;
            As[k][m] = src[(size_t)(row0 + m)*Dd + k0 + k];
        }
        for (int l = tid; l < 32*64; l += 256) {
            int n = l & 63, k = l >> 6;
            Bs[k][n] = W[(size_t)(k0 + k)*Dd + col0 + n];
        }
        __syncthreads();
        #pragma unroll
        for (int k = 0; k < 32; k++) {
            float4 a4 = *(const float4*)&As[k][ty*4];
            float4 b4 = *(const float4*)&Bs[k][tx*4];
            float a[4] = {a4.x, a4.y, a4.z, a4.w};
            float b[4] = {b4.x, b4.y, b4.z, b4.w};
            #pragma unroll
            for (int i = 0; i < 4; i++)
                #pragma unroll
                for (int j = 0; j < 4; j++)
                    acc[i][j] += a[i] * b[j];
        }
        __syncthreads();
    }
    #pragma unroll
    for (int i = 0; i < 4; i++) {
        float4 v = make_float4(acc[i][0], acc[i][1], acc[i][2], acc[i][3]);
        *(float4*)&dst[(size_t)(row0 + ty*4 + i)*Dd + col0 + tx*4] = v;
    }
}

// ---------------------------------------------------------------------------
// Kernel 2: row norms q2, k2. One warp per row.
// ---------------------------------------------------------------------------
__global__ __launch_bounds__(256) void norms_kernel()
{
    int warp = (blockIdx.x * blockDim.x + threadIdx.x) >> 5;
    int lane = threadIdx.x & 31;
    if (warp >= NR) return;
    const float* q = g_Q + (size_t)warp * Dd;
    const float* k = g_K + (size_t)warp * Dd;
    float sq = 0.f, sk = 0.f;
    for (int i = lane; i < Dd; i += 32) {
        float a = q[i]; sq += a * a;
        float b = k[i]; sk += b * b;
    }
    #pragma unroll
    for (int o = 16; o; o >>= 1) {
        sq += __shfl_xor_sync(0xFFFFFFFFu, sq, o);
        sk += __shfl_xor_sync(0xFFFFFFFFu, sk, o);
    }
    if (lane == 0) { g_q2[warp] = sq; g_k2[warp] = sk; }
}

// ---------------------------------------------------------------------------
// Kernel 3: d2[b,s,t] = max(q2[s]+k2[t]-2*Q_s.K_t, 0), causal tiles only.
// float4 microtile. grid: (Ss/64 (t), Ss/64 (s), Bb)
// ---------------------------------------------------------------------------
__global__ __launch_bounds__(256) void d2_kernel()
{
    const int b  = blockIdx.z;
    const int s0 = blockIdx.y * 64;
    const int t0 = blockIdx.x * 64;
    if (t0 > s0 + 63) return;   // fully above diagonal

    const float* Qb = g_Q + (size_t)b*Ss*Dd;
    const float* Kb = g_K + (size_t)b*Ss*Dd;

    __shared__ float As[32][68];  // Q:  As[k][m]
    __shared__ float Bs[32][68];  // K:  Bs[k][n]

    const int tid = threadIdx.x;
    const int tx = tid & 15;
    const int ty = tid >> 4;

    float acc[4][4] = {};
    for (int k0 = 0; k0 < Dd; k0 += 32) {
        for (int l = tid; l < 64*32; l += 256) {
            int k = l & 31, m = l >> 5;
            As[k][m] = Qb[(size_t)(s0 + m)*Dd + k0 + k];
        }
        for (int l = tid; l < 64*32; l += 256) {
            int k = l & 31, n = l >> 5;
            Bs[k][n] = Kb[(size_t)(t0 + n)*Dd + k0 + k];
        }
        __syncthreads();
        #pragma unroll
        for (int k = 0; k < 32; k++) {
            float4 a4 = *(const float4*)&As[k][ty*4];
            float4 b4 = *(const float4*)&Bs[k][tx*4];
            float a[4]  = {a4.x, a4.y, a4.z, a4.w};
            float bv[4] = {b4.x, b4.y, b4.z, b4.w};
            #pragma unroll
            for (int i = 0; i < 4; i++)
                #pragma unroll
                for (int j = 0; j < 4; j++)
                    acc[i][j] += a[i] * bv[j];
        }
        __syncthreads();
    }

    float* d2b = g_d2 + (size_t)b*Ss*Ss;
    #pragma unroll
    for (int i = 0; i < 4; i++) {
        int s = s0 + ty*4 + i;
        float q2v = g_q2[b*Ss + s];
        float4 o;
        float* op = &o.x;
        #pragma unroll
        for (int j = 0; j < 4; j++) {
            int t = t0 + tx*4 + j;
            float v = q2v + g_k2[b*Ss + t] - 2.0f * acc[i][j];
            op[j] = fmaxf(v, 0.0f);
        }
        *(float4*)&d2b[(size_t)s*Ss + t0 + tx*4] = o;
    }
}

// ---------------------------------------------------------------------------
// Kernel 4 (split-t): partial O += exp(coef*d2) @ V over one chunk of 4
// t-tiles (256 keys). Accumulates into the LEADER head's slice of out via
// atomicAdd (out must be zeroed before). Non-leader heads exit; a broadcast
// kernel later copies leader -> duplicates.
// grid: (32 s_tiles [reversed], 8 max chunks, Bb*4dchunk*Hh)  block: 256
// ---------------------------------------------------------------------------
#define TCH 4   // t-tiles per chunk

__global__ __launch_bounds__(256, 4) void attn_kernel(
    const float* __restrict__ gamma, float* __restrict__ out)
{
    const int s_tile = (int)gridDim.x - 1 - (int)blockIdx.x;  // longest first
    const int chunk  = blockIdx.y;
    if (chunk > (s_tile >> 2)) return;          // chunk >= ceil((s_tile+1)/4)

    const int z = blockIdx.z;
    const int h      = z & 7;
    const int dchunk = (z >> 3) & 3;
    const int b      = z >> 5;

    const float gh = gamma[h];
    for (int h2 = 0; h2 < h; h2++)
        if (gamma[h2] == gh) return;            // not the leader for this gamma
    const float coef = -1.0f / (-2.0f * gh + 1e-6f);

    const int s0 = s_tile * 64;
    const int d0 = dchunk * 64;
    const int tlo = chunk * (TCH*64);
    const int thi = min(s0 + 64, tlo + TCH*64);

    __shared__ float Ps[64][65];   // Ps[s_row][t]
    __shared__ float Vs[64][64];   // Vs[t][d_col]

    const int tid = threadIdx.x;
    const int tx = tid & 15;       // cols c = tx*4 + j
    const int ty = tid >> 4;       // rows r = ty*4 + i

    float acc[4][4] = {};

    const float* Vb  = g_V  + (size_t)b*Ss*Dd;
    const float* d2b = g_d2 + (size_t)b*Ss*Ss;

    for (int t0 = tlo; t0 < thi; t0 += 64) {
        const bool diag = (t0 == s0);
        // load + exp the d2 tile (coalesced global, conflict-free STS)
        for (int l = tid; l < 64*64; l += 256) {
            int c = l & 63, r = l >> 6;
            float d2v = d2b[(size_t)(s0 + r)*Ss + t0 + c];
            float pv = __expf(coef * d2v);
            if (diag && (c > r)) pv = 0.0f;    // causal mask inside diag tile
            Ps[r][c] = pv;
        }
        // load V tile chunk
        for (int l = tid; l < 64*64; l += 256) {
            int c = l & 63, r = l >> 6;
            Vs[r][c] = Vb[(size_t)(t0 + r)*Dd + d0 + c];
        }
        __syncthreads();
        #pragma unroll 4
        for (int t = 0; t < 64; t++) {
            float pv[4];
            #pragma unroll
            for (int i = 0; i < 4; i++) pv[i] = Ps[ty*4 + i][t];
            float4 v4 = *(const float4*)&Vs[t][tx*4];
            float vv[4] = {v4.x, v4.y, v4.z, v4.w};
            #pragma unroll
            for (int i = 0; i < 4; i++)
                #pragma unroll
                for (int j = 0; j < 4; j++)
                    acc[i][j] += pv[i] * vv[j];
        }
        __syncthreads();
    }

    // accumulate into leader head's output slice
    float* o = out + ((size_t)(b*Hh + h)*Ss)*Dd;
    #pragma unroll
    for (int i = 0; i < 4; i++) {
        size_t row = (size_t)(s0 + ty*4 + i)*Dd + d0 + tx*4;
        #pragma unroll
        for (int j = 0; j < 4; j++)
            atomicAdd(&o[row + j], acc[i][j]);
    }
}

// ---------------------------------------------------------------------------
// Kernel 5: broadcast leader head output to duplicate-gamma heads.
// grid: (S*D/1024, Hh, Bb)  block: 256, one float4 per thread.
// ---------------------------------------------------------------------------
__global__ __launch_bounds__(256) void bcast_kernel(
    const float* __restrict__ gamma, float* __restrict__ out)
{
    const int h = blockIdx.y, b = blockIdx.z;
    const float gh = gamma[h];
    int leader = h;
    for (int h2 = 0; h2 < h; h2++)
        if (gamma[h2] == gh) { leader = h2; break; }
    if (leader == h) return;

    size_t idx = ((size_t)blockIdx.x * 256 + threadIdx.x) * 4;
    const float4 v = *(const float4*)&out[((size_t)(b*Hh + leader)*Ss)*Dd + idx];
    *(float4*)&out[((size_t)(b*Hh + h)*Ss)*Dd + idx] = v;
}

// ---------------------------------------------------------------------------
extern "C" void kernel_launch(void* const* d_in, const int* in_sizes, int n_in,
                              void* d_out, int out_size)
{
    // metadata order: x, e, p, W_q, W_k, W_v, gamma   (x unused: use_ppe path)
    const float* e     = (const float*)d_in[1];
    const float* p     = (const float*)d_in[2];
    const float* Wq    = (const float*)d_in[3];
    const float* Wk    = (const float*)d_in[4];
    const float* Wv    = (const float*)d_in[5];
    const float* gamma = (const float*)d_in[6];
    float* out = (float*)d_out;

    dim3 gproj(NR/64, Dd/64, 3);
    proj_kernel<<<gproj, 256>>>(p, e, Wq, Wk, Wv);

    norms_kernel<<<(NR*32)/256, 256>>>();

    dim3 gd2(Ss/64, Ss/64, Bb);
    d2_kernel<<<gd2, 256>>>();

    // zero output: attn accumulates with atomicAdd
    cudaMemsetAsync(d_out, 0, (size_t)out_size * sizeof(float));

    dim3 gattn(Ss/64, 8 /*max chunks*/, Bb * 4 /*dchunk*/ * Hh);
    attn_kernel<<<gattn, 256>>>(gamma, out);

    dim3 gb((Ss*Dd)/1024, Hh, Bb);
    bcast_kernel<<<gb, 256>>>(gamma, out);
}

// round 6
// speedup vs baseline: 2.3001x; 1.2130x over previous
#include <cuda_runtime.h>
#include <cuda_bf16.h>
#include <cstdint>

// Problem constants
#define Bb 2
#define Ss 2048
#define Dd 256
#define Hh 8
#define NR (Bb*Ss)

// Scratch
__device__ float g_Q[Bb*Ss*Dd];
__device__ float g_K[Bb*Ss*Dd];
__device__ float g_V[Bb*Ss*Dd];
__device__ float g_q2[NR];
__device__ float g_k2[NR];
__device__ float g_d2[(size_t)Bb*Ss*Ss];   // 33.5 MB, causal part written

// ===================== mma.sync helpers =====================
__device__ __forceinline__ uint32_t f2tf32(float f) {
    uint32_t r;
    asm("cvt.rna.tf32.f32 %0, %1;" : "=r"(r) : "f"(f));
    return r;
}
__device__ __forceinline__ void mma_tf32(float* c, const uint32_t* a, const uint32_t* b) {
    asm volatile(
        "mma.sync.aligned.m16n8k8.row.col.f32.tf32.tf32.f32 "
        "{%0,%1,%2,%3}, {%4,%5,%6,%7}, {%8,%9}, {%0,%1,%2,%3};"
        : "+f"(c[0]), "+f"(c[1]), "+f"(c[2]), "+f"(c[3])
        : "r"(a[0]), "r"(a[1]), "r"(a[2]), "r"(a[3]), "r"(b[0]), "r"(b[1]));
}
__device__ __forceinline__ void mma_bf16(float* c, const uint32_t* a, const uint32_t* b) {
    asm volatile(
        "mma.sync.aligned.m16n8k16.row.col.f32.bf16.bf16.f32 "
        "{%0,%1,%2,%3}, {%4,%5,%6,%7}, {%8,%9}, {%0,%1,%2,%3};"
        : "+f"(c[0]), "+f"(c[1]), "+f"(c[2]), "+f"(c[3])
        : "r"(a[0]), "r"(a[1]), "r"(a[2]), "r"(a[3]), "r"(b[0]), "r"(b[1]));
}
__device__ __forceinline__ uint32_t pack_bf16x2(float lo_val, float hi_val) {
    __nv_bfloat16 l = __float2bfloat16(lo_val);
    __nv_bfloat16 h = __float2bfloat16(hi_val);
    return (uint32_t)__bfloat16_as_ushort(l) | ((uint32_t)__bfloat16_as_ushort(h) << 16);
}

// ---------------------------------------------------------------------------
// Kernel 1: projections (SIMT fp32 SGEMM, unchanged from R4)
// ---------------------------------------------------------------------------
__global__ __launch_bounds__(256) void proj_kernel(
    const float* __restrict__ p, const float* __restrict__ e,
    const float* __restrict__ Wq, const float* __restrict__ Wk,
    const float* __restrict__ Wv)
{
    const int which = blockIdx.z;
    const float* src = (which == 2) ? e : p;
    const float* W   = (which == 0) ? Wq : (which == 1) ? Wk : Wv;
    float* dst       = (which == 0) ? g_Q : (which == 1) ? g_K : g_V;

    const int row0 = blockIdx.x * 64;
    const int col0 = blockIdx.y * 64;

    __shared__ float As[32][68];
    __shared__ float Bs[32][68];

    const int tid = threadIdx.x;
    const int tx = tid & 15;
    const int ty = tid >> 4;

    float acc[4][4] = {};
    for (int k0 = 0; k0 < Dd; k0 += 32) {
        for (int l = tid; l < 64*32; l += 256) {
            int k = l & 31, m = l >> 5;
            As[k][m] = src[(size_t)(row0 + m)*Dd + k0 + k];
        }
        for (int l = tid; l < 32*64; l += 256) {
            int n = l & 63, k = l >> 6;
            Bs[k][n] = W[(size_t)(k0 + k)*Dd + col0 + n];
        }
        __syncthreads();
        #pragma unroll
        for (int k = 0; k < 32; k++) {
            float4 a4 = *(const float4*)&As[k][ty*4];
            float4 b4 = *(const float4*)&Bs[k][tx*4];
            float a[4] = {a4.x, a4.y, a4.z, a4.w};
            float b[4] = {b4.x, b4.y, b4.z, b4.w};
            #pragma unroll
            for (int i = 0; i < 4; i++)
                #pragma unroll
                for (int j = 0; j < 4; j++)
                    acc[i][j] += a[i] * b[j];
        }
        __syncthreads();
    }
    #pragma unroll
    for (int i = 0; i < 4; i++) {
        float4 v = make_float4(acc[i][0], acc[i][1], acc[i][2], acc[i][3]);
        *(float4*)&dst[(size_t)(row0 + ty*4 + i)*Dd + col0 + tx*4] = v;
    }
}

// ---------------------------------------------------------------------------
// Kernel 2: row norms
// ---------------------------------------------------------------------------
__global__ __launch_bounds__(256) void norms_kernel()
{
    int warp = (blockIdx.x * blockDim.x + threadIdx.x) >> 5;
    int lane = threadIdx.x & 31;
    if (warp >= NR) return;
    const float* q = g_Q + (size_t)warp * Dd;
    const float* k = g_K + (size_t)warp * Dd;
    float sq = 0.f, sk = 0.f;
    for (int i = lane; i < Dd; i += 32) {
        float a = q[i]; sq += a * a;
        float b = k[i]; sk += b * b;
    }
    #pragma unroll
    for (int o = 16; o; o >>= 1) {
        sq += __shfl_xor_sync(0xFFFFFFFFu, sq, o);
        sk += __shfl_xor_sync(0xFFFFFFFFu, sk, o);
    }
    if (lane == 0) { g_q2[warp] = sq; g_k2[warp] = sk; }
}

// ---------------------------------------------------------------------------
// Kernel 3: d2 via split-tf32 mma.sync (m16n8k8, 3 products).
// Tile 128(s) x 64(t), K=256 in slabs of 32.
// grid: (32 t-tiles, 16 s-tiles, Bb)  block: 256 (8 warps of 32x32 subtiles)
// ---------------------------------------------------------------------------
#define QSTR 137   // 128+9: stage conflict-free, frag-load ~2-way
#define KSTR 73    // 64+9
#define D2_SMEM ((2*32*QSTR + 2*32*KSTR)*4)   // 53760 B

__global__ __launch_bounds__(256) void d2_mma_kernel()
{
    const int si = blockIdx.y, tt = blockIdx.x, b = blockIdx.z;
    if (tt > 2*si + 1) return;                 // fully above diagonal
    const int s0 = si*128, t0 = tt*64;

    extern __shared__ float sm[];
    float* Qh = sm;
    float* Ql = Qh + 32*QSTR;
    float* Kh = Ql + 32*QSTR;
    float* Kl = Kh + 32*KSTR;
    const uint32_t* uQh = (const uint32_t*)Qh;
    const uint32_t* uQl = (const uint32_t*)Ql;
    const uint32_t* uKh = (const uint32_t*)Kh;
    const uint32_t* uKl = (const uint32_t*)Kl;

    const int tid = threadIdx.x, lane = tid & 31, wid = tid >> 5;
    const int wm = wid & 3, wn = wid >> 2;      // 4x2 warp grid of 32x32

    const float* Qg = g_Q + ((size_t)(b*Ss + s0))*Dd;
    const float* Kg = g_K + ((size_t)(b*Ss + t0))*Dd;

    float C[2][4][4] = {};

    for (int k0 = 0; k0 < Dd; k0 += 32) {
        __syncthreads();   // protect prior-iter frag reads
        // stage Q slab 128x32 -> [k][m] hi/lo tf32
        for (int l = tid; l < 1024; l += 256) {
            int m = l >> 3, c = l & 7;
            float4 v = *(const float4*)(Qg + (size_t)m*Dd + k0 + c*4);
            float f[4] = {v.x, v.y, v.z, v.w};
            #pragma unroll
            for (int j = 0; j < 4; j++) {
                uint32_t hb = f2tf32(f[j]);
                float hf = __uint_as_float(hb);
                uint32_t lb = f2tf32(f[j] - hf);
                int k = c*4 + j;
                Qh[k*QSTR + m] = __uint_as_float(hb);
                Ql[k*QSTR + m] = __uint_as_float(lb);
            }
        }
        // stage K slab 64x32 -> [k][t] hi/lo tf32
        for (int l = tid; l < 512; l += 256) {
            int t = l >> 3, c = l & 7;
            float4 v = *(const float4*)(Kg + (size_t)t*Dd + k0 + c*4);
            float f[4] = {v.x, v.y, v.z, v.w};
            #pragma unroll
            for (int j = 0; j < 4; j++) {
                uint32_t hb = f2tf32(f[j]);
                float hf = __uint_as_float(hb);
                uint32_t lb = f2tf32(f[j] - hf);
                int k = c*4 + j;
                Kh[k*KSTR + t] = __uint_as_float(hb);
                Kl[k*KSTR + t] = __uint_as_float(lb);
            }
        }
        __syncthreads();

        const int r = lane >> 2, cc = lane & 3;
        #pragma unroll
        for (int ks = 0; ks < 4; ks++) {
            uint32_t ah[2][4], al[2][4];
            #pragma unroll
            for (int mf = 0; mf < 2; mf++) {
                int mrow = wm*32 + mf*16 + r;
                int kc = ks*8 + cc;
                ah[mf][0] = uQh[kc*QSTR + mrow];
                ah[mf][1] = uQh[kc*QSTR + mrow + 8];
                ah[mf][2] = uQh[(kc+4)*QSTR + mrow];
                ah[mf][3] = uQh[(kc+4)*QSTR + mrow + 8];
                al[mf][0] = uQl[kc*QSTR + mrow];
                al[mf][1] = uQl[kc*QSTR + mrow + 8];
                al[mf][2] = uQl[(kc+4)*QSTR + mrow];
                al[mf][3] = uQl[(kc+4)*QSTR + mrow + 8];
            }
            uint32_t bh[4][2], bl[4][2];
            #pragma unroll
            for (int nf = 0; nf < 4; nf++) {
                int ncol = wn*32 + nf*8 + r;
                int kc = ks*8 + cc;
                bh[nf][0] = uKh[kc*KSTR + ncol];
                bh[nf][1] = uKh[(kc+4)*KSTR + ncol];
                bl[nf][0] = uKl[kc*KSTR + ncol];
                bl[nf][1] = uKl[(kc+4)*KSTR + ncol];
            }
            #pragma unroll
            for (int mf = 0; mf < 2; mf++)
                #pragma unroll
                for (int nf = 0; nf < 4; nf++) {
                    mma_tf32(C[mf][nf], ah[mf], bh[nf]);
                    mma_tf32(C[mf][nf], ah[mf], bl[nf]);
                    mma_tf32(C[mf][nf], al[mf], bh[nf]);
                }
        }
    }

    // epilogue: d2 = max(q2 + k2 - 2S, 0)
    float* d2b = g_d2 + (size_t)b*Ss*Ss;
    const int r = lane >> 2, q = lane & 3;
    #pragma unroll
    for (int mf = 0; mf < 2; mf++) {
        int s = s0 + wm*32 + mf*16 + r;
        float q2a = g_q2[b*Ss + s];
        float q2c = g_q2[b*Ss + s + 8];
        #pragma unroll
        for (int nf = 0; nf < 4; nf++) {
            int t = t0 + wn*32 + nf*8 + 2*q;
            float k2a = g_k2[b*Ss + t];
            float k2b = g_k2[b*Ss + t + 1];
            float2 v0 = make_float2(fmaxf(q2a + k2a - 2.0f*C[mf][nf][0], 0.0f),
                                    fmaxf(q2a + k2b - 2.0f*C[mf][nf][1], 0.0f));
            float2 v1 = make_float2(fmaxf(q2c + k2a - 2.0f*C[mf][nf][2], 0.0f),
                                    fmaxf(q2c + k2b - 2.0f*C[mf][nf][3], 0.0f));
            *(float2*)&d2b[(size_t)s*Ss + t]       = v0;
            *(float2*)&d2b[(size_t)(s+8)*Ss + t]   = v1;
        }
    }
}

// ---------------------------------------------------------------------------
// Kernel 4: attn via split-bf16 mma.sync (m16n8k16, 3 products).
// Tile 128(s) x 64(d), chunk of 4 t-tiles of 64; atomicAdd into leader head.
// grid: (16 s-tiles reversed, 8 chunks, Bb*4dchunk*Hh)  block: 256
// ---------------------------------------------------------------------------
#define PSTR 36    // uint32 stride: bank = 4*row + pair, conflict-free
#define VSTR 36
#define TSTR 65
#define AT_SMEM ((2*128*PSTR + 2*64*VSTR + 64*TSTR)*4)   // 71936 B

__global__ __launch_bounds__(256) void attn_mma_kernel(
    const float* __restrict__ gamma, float* __restrict__ out)
{
    const int si = (int)gridDim.x - 1 - (int)blockIdx.x;   // biggest first
    const int chunk = blockIdx.y;
    const int n_t = 2*si + 2;
    if (4*chunk >= n_t) return;

    const int z = blockIdx.z;
    const int b = z >> 5, dch = (z >> 3) & 3, h = z & 7;
    const float gh = gamma[h];
    for (int h2 = 0; h2 < h; h2++)
        if (gamma[h2] == gh) return;                        // leader only
    const float coef = -1.0f / (-2.0f * gh + 1e-6f);

    const int s0 = si*128, d0 = dch*64;

    extern __shared__ uint32_t smu[];
    uint32_t* Psh = smu;                    // P hi bf16x2 [s][tpair]
    uint32_t* Psl = Psh + 128*PSTR;
    uint32_t* Vsh = Psl + 128*PSTR;         // V hi bf16x2 [d][tpair]
    uint32_t* Vsl = Vsh + 64*VSTR;
    float*    Tst = (float*)(Vsl + 64*VSTR);  // f32 transpose stage [t][d]

    const int tid = threadIdx.x, lane = tid & 31, wid = tid >> 5;
    const int wm = wid & 3, wn = wid >> 2;   // 4x2 warp grid of 32x32

    const float* d2b = g_d2 + (size_t)b*Ss*Ss;
    const float* Vb  = g_V  + (size_t)b*Ss*Dd;

    float C[2][4][4] = {};

    const int tt0 = 4*chunk, tt1 = min(tt0 + 4, n_t);
    for (int tt = tt0; tt < tt1; tt++) {
        const int t0 = tt*64;
        __syncthreads();    // protect previous-iter frag reads

        // stage P = exp(coef * d2), causal-masked, split bf16 hi/lo
        for (int l = tid; l < 4096; l += 256) {
            int r = l >> 5, pr = l & 31;
            int sg = s0 + r, tg = t0 + 2*pr;
            float2 dv = *(const float2*)(d2b + (size_t)sg*Ss + tg);
            float p0 = (tg     > sg) ? 0.0f : __expf(coef * dv.x);
            float p1 = (tg + 1 > sg) ? 0.0f : __expf(coef * dv.y);
            __nv_bfloat16 h0 = __float2bfloat16(p0);
            __nv_bfloat16 h1 = __float2bfloat16(p1);
            float l0 = p0 - __bfloat162float(h0);
            float l1 = p1 - __bfloat162float(h1);
            Psh[r*PSTR + pr] = (uint32_t)__bfloat16_as_ushort(h0)
                             | ((uint32_t)__bfloat16_as_ushort(h1) << 16);
            Psl[r*PSTR + pr] = pack_bf16x2(l0, l1);
        }
        // stage V f32 [t][d] chunk
        for (int l = tid; l < 1024; l += 256) {
            int t = l >> 4, c = l & 15;
            float4 v = *(const float4*)(Vb + (size_t)(t0 + t)*Dd + d0 + c*4);
            Tst[t*TSTR + c*4 + 0] = v.x;
            Tst[t*TSTR + c*4 + 1] = v.y;
            Tst[t*TSTR + c*4 + 2] = v.z;
            Tst[t*TSTR + c*4 + 3] = v.w;
        }
        __syncthreads();
        // transpose + split V -> [d][tpair] bf16x2 hi/lo
        for (int l = tid; l < 2048; l += 256) {
            int d = l >> 5, pr = l & 31;
            float v0 = Tst[(2*pr)*TSTR + d];
            float v1 = Tst[(2*pr + 1)*TSTR + d];
            __nv_bfloat16 h0 = __float2bfloat16(v0);
            __nv_bfloat16 h1 = __float2bfloat16(v1);
            Vsh[d*VSTR + pr] = (uint32_t)__bfloat16_as_ushort(h0)
                             | ((uint32_t)__bfloat16_as_ushort(h1) << 16);
            Vsl[d*VSTR + pr] = pack_bf16x2(v0 - __bfloat162float(h0),
                                           v1 - __bfloat162float(h1));
        }
        __syncthreads();

        const int r = lane >> 2, cc = lane & 3;
        #pragma unroll
        for (int ks = 0; ks < 4; ks++) {
            uint32_t ah[2][4], al[2][4];
            #pragma unroll
            for (int mf = 0; mf < 2; mf++) {
                int srow = wm*32 + mf*16 + r;
                int pc = ks*8 + cc;
                ah[mf][0] = Psh[srow*PSTR + pc];
                ah[mf][1] = Psh[(srow+8)*PSTR + pc];
                ah[mf][2] = Psh[srow*PSTR + pc + 4];
                ah[mf][3] = Psh[(srow+8)*PSTR + pc + 4];
                al[mf][0] = Psl[srow*PSTR + pc];
                al[mf][1] = Psl[(srow+8)*PSTR + pc];
                al[mf][2] = Psl[srow*PSTR + pc + 4];
                al[mf][3] = Psl[(srow+8)*PSTR + pc + 4];
            }
            uint32_t bh[4][2], bl[4][2];
            #pragma unroll
            for (int nf = 0; nf < 4; nf++) {
                int dcol = wn*32 + nf*8 + r;
                int pc = ks*8 + cc;
                bh[nf][0] = Vsh[dcol*VSTR + pc];
                bh[nf][1] = Vsh[dcol*VSTR + pc + 4];
                bl[nf][0] = Vsl[dcol*VSTR + pc];
                bl[nf][1] = Vsl[dcol*VSTR + pc + 4];
            }
            #pragma unroll
            for (int mf = 0; mf < 2; mf++)
                #pragma unroll
                for (int nf = 0; nf < 4; nf++) {
                    mma_bf16(C[mf][nf], ah[mf], bh[nf]);
                    mma_bf16(C[mf][nf], ah[mf], bl[nf]);
                    mma_bf16(C[mf][nf], al[mf], bh[nf]);
                }
        }
    }

    // epilogue: accumulate into leader head's output slice
    float* o = out + ((size_t)(b*Hh + h)*Ss)*Dd;
    const int r = lane >> 2, q = lane & 3;
    #pragma unroll
    for (int mf = 0; mf < 2; mf++) {
        int s = s0 + wm*32 + mf*16 + r;
        #pragma unroll
        for (int nf = 0; nf < 4; nf++) {
            int d = d0 + wn*32 + nf*8 + 2*q;
            atomicAdd(&o[(size_t)s*Dd + d],         C[mf][nf][0]);
            atomicAdd(&o[(size_t)s*Dd + d + 1],     C[mf][nf][1]);
            atomicAdd(&o[(size_t)(s+8)*Dd + d],     C[mf][nf][2]);
            atomicAdd(&o[(size_t)(s+8)*Dd + d + 1], C[mf][nf][3]);
        }
    }
}

// ---------------------------------------------------------------------------
// Kernel 5: broadcast leader head output to duplicate-gamma heads.
// ---------------------------------------------------------------------------
__global__ __launch_bounds__(256) void bcast_kernel(
    const float* __restrict__ gamma, float* __restrict__ out)
{
    const int h = blockIdx.y, b = blockIdx.z;
    const float gh = gamma[h];
    int leader = h;
    for (int h2 = 0; h2 < h; h2++)
        if (gamma[h2] == gh) { leader = h2; break; }
    if (leader == h) return;

    size_t idx = ((size_t)blockIdx.x * 256 + threadIdx.x) * 4;
    const float4 v = *(const float4*)&out[((size_t)(b*Hh + leader)*Ss)*Dd + idx];
    *(float4*)&out[((size_t)(b*Hh + h)*Ss)*Dd + idx] = v;
}

// ---------------------------------------------------------------------------
extern "C" void kernel_launch(void* const* d_in, const int* in_sizes, int n_in,
                              void* d_out, int out_size)
{
    // metadata order: x, e, p, W_q, W_k, W_v, gamma
    const float* e     = (const float*)d_in[1];
    const float* p     = (const float*)d_in[2];
    const float* Wq    = (const float*)d_in[3];
    const float* Wk    = (const float*)d_in[4];
    const float* Wv    = (const float*)d_in[5];
    const float* gamma = (const float*)d_in[6];
    float* out = (float*)d_out;

    static bool attr_set = false;
    if (!attr_set) {
        cudaFuncSetAttribute(d2_mma_kernel,
                             cudaFuncAttributeMaxDynamicSharedMemorySize, D2_SMEM);
        cudaFuncSetAttribute(attn_mma_kernel,
                             cudaFuncAttributeMaxDynamicSharedMemorySize, AT_SMEM);
        attr_set = true;
    }

    dim3 gproj(NR/64, Dd/64, 3);
    proj_kernel<<<gproj, 256>>>(p, e, Wq, Wk, Wv);

    norms_kernel<<<(NR*32)/256, 256>>>();

    dim3 gd2(32, 16, Bb);
    d2_mma_kernel<<<gd2, 256, D2_SMEM>>>();

    cudaMemsetAsync(d_out, 0, (size_t)out_size * sizeof(float));

    dim3 gattn(16, 8, Bb * 4 * Hh);
    attn_mma_kernel<<<gattn, 256, AT_SMEM>>>(gamma, out);

    dim3 gb((Ss*Dd)/1024, Hh, Bb);
    bcast_kernel<<<gb, 256>>>(gamma, out);
}